// round 3
// baseline (speedup 1.0000x reference)
#include <cuda_runtime.h>

// K_attention: out = x + exp(-max(||xi||^2 - 2<xi,xj> + ||xj||^2, 0) * sigma) @ x
// B=32, T=2048, C=64, fp32.

#define BATCH   32
#define TDIM    2048
#define CDIM    64
#define BM      64
#define BN      64
#define THREADS 256
#define STRIDE  (CDIM + 4)   // 68 floats; multiple of 4 -> float4-aligned rows

// smem layout (floats):
//   Qt[CDIM][STRIDE]  transposed Q tile: Qt[c][row]
//   Kt[CDIM][STRIDE]  transposed K tile: Kt[c][col]
//   Ks[BN][STRIDE]    row-major K tile:  Ks[s][c]   (value operand for stage 2)
//   Ws[BM][STRIDE]    kernel-weight tile
//   sqq[BM], sqk[BN]
#define SMEM_FLOATS (4 * CDIM * STRIDE + BM + BN)
#define SMEM_BYTES  (SMEM_FLOATS * 4)

__global__ __launch_bounds__(THREADS)
void k_attention_kernel(const float* __restrict__ x,
                        const float* __restrict__ r_sigma,
                        float* __restrict__ out) {
    extern __shared__ float smem[];
    float* Qt  = smem;
    float* Kt  = Qt + CDIM * STRIDE;
    float* Ks  = Kt + CDIM * STRIDE;
    float* Ws  = Ks + BN * STRIDE;
    float* sqq = Ws + BM * STRIDE;
    float* sqk = sqq + BM;

    const int b     = blockIdx.y;
    const int qbase = blockIdx.x * BM;
    const float* xb = x + (size_t)b * TDIM * CDIM;
    float* ob       = out + (size_t)b * TDIM * CDIM;
    const float sigma = r_sigma[0];

    const int tid = threadIdx.x;
    const int tx  = tid & 15;        // 16 col-groups
    const int ty  = tid >> 4;        // 16 row-groups
    const int tx4 = tx * 4;
    const int ty4 = ty * 4;

    // ---- load Q tile (transposed into Qt[c][row]) ----
    #pragma unroll
    for (int it = 0; it < (BM * CDIM) / (4 * THREADS); ++it) {
        int idx = tid + it * THREADS;      // float4 index
        int row = idx >> 4;                // 16 float4 per row of 64 floats
        int c4  = (idx & 15) * 4;
        float4 v = *reinterpret_cast<const float4*>(&xb[(qbase + row) * CDIM + c4]);
        Qt[(c4 + 0) * STRIDE + row] = v.x;
        Qt[(c4 + 1) * STRIDE + row] = v.y;
        Qt[(c4 + 2) * STRIDE + row] = v.z;
        Qt[(c4 + 3) * STRIDE + row] = v.w;
    }
    __syncthreads();

    // ---- squared norms of Q rows ----
    if (tid < BM) {
        float s = 0.f;
        #pragma unroll 16
        for (int c = 0; c < CDIM; ++c) {
            float v = Qt[c * STRIDE + tid];
            s = fmaf(v, v, s);
        }
        sqq[tid] = s;
    }

    float acc[4][4] = {{0.f}};

    for (int kt = 0; kt < TDIM / BN; ++kt) {
        const int kbase = kt * BN;
        __syncthreads();   // protects Kt/Ks/Ws/sqk reuse (and sqq on iter 0)

        // ---- load K tile (row-major Ks + transposed Kt) ----
        #pragma unroll
        for (int it = 0; it < (BN * CDIM) / (4 * THREADS); ++it) {
            int idx = tid + it * THREADS;
            int row = idx >> 4;
            int c4  = (idx & 15) * 4;
            float4 v = *reinterpret_cast<const float4*>(&xb[(kbase + row) * CDIM + c4]);
            *reinterpret_cast<float4*>(&Ks[row * STRIDE + c4]) = v;
            Kt[(c4 + 0) * STRIDE + row] = v.x;
            Kt[(c4 + 1) * STRIDE + row] = v.y;
            Kt[(c4 + 2) * STRIDE + row] = v.z;
            Kt[(c4 + 3) * STRIDE + row] = v.w;
        }
        __syncthreads();

        if (tid < BN) {
            float s = 0.f;
            #pragma unroll 16
            for (int c = 0; c < CDIM; ++c) {
                float v = Kt[c * STRIDE + tid];
                s = fmaf(v, v, s);
            }
            sqk[tid] = s;
        }
        __syncthreads();

        // ---- stage 1: inner products -> W tile ----
        float wv[4][4] = {{0.f}};
        #pragma unroll 8
        for (int c = 0; c < CDIM; ++c) {
            float4 a  = *reinterpret_cast<const float4*>(&Qt[c * STRIDE + ty4]);
            float4 bv = *reinterpret_cast<const float4*>(&Kt[c * STRIDE + tx4]);
            wv[0][0] = fmaf(a.x, bv.x, wv[0][0]);
            wv[0][1] = fmaf(a.x, bv.y, wv[0][1]);
            wv[0][2] = fmaf(a.x, bv.z, wv[0][2]);
            wv[0][3] = fmaf(a.x, bv.w, wv[0][3]);
            wv[1][0] = fmaf(a.y, bv.x, wv[1][0]);
            wv[1][1] = fmaf(a.y, bv.y, wv[1][1]);
            wv[1][2] = fmaf(a.y, bv.z, wv[1][2]);
            wv[1][3] = fmaf(a.y, bv.w, wv[1][3]);
            wv[2][0] = fmaf(a.z, bv.x, wv[2][0]);
            wv[2][1] = fmaf(a.z, bv.y, wv[2][1]);
            wv[2][2] = fmaf(a.z, bv.z, wv[2][2]);
            wv[2][3] = fmaf(a.z, bv.w, wv[2][3]);
            wv[3][0] = fmaf(a.w, bv.x, wv[3][0]);
            wv[3][1] = fmaf(a.w, bv.y, wv[3][1]);
            wv[3][2] = fmaf(a.w, bv.z, wv[3][2]);
            wv[3][3] = fmaf(a.w, bv.w, wv[3][3]);
        }

        float sa[4], sb[4];
        #pragma unroll
        for (int i = 0; i < 4; ++i) sa[i] = sqq[ty4 + i];
        #pragma unroll
        for (int j = 0; j < 4; ++j) sb[j] = sqk[tx4 + j];

        #pragma unroll
        for (int i = 0; i < 4; ++i) {
            float4 wrow;
            float d0 = fmaxf(sa[i] + sb[0] - 2.f * wv[i][0], 0.f);
            float d1 = fmaxf(sa[i] + sb[1] - 2.f * wv[i][1], 0.f);
            float d2 = fmaxf(sa[i] + sb[2] - 2.f * wv[i][2], 0.f);
            float d3 = fmaxf(sa[i] + sb[3] - 2.f * wv[i][3], 0.f);
            wrow.x = __expf(-d0 * sigma);
            wrow.y = __expf(-d1 * sigma);
            wrow.z = __expf(-d2 * sigma);
            wrow.w = __expf(-d3 * sigma);
            *reinterpret_cast<float4*>(&Ws[(ty4 + i) * STRIDE + tx4]) = wrow;
        }
        __syncthreads();

        // ---- stage 2: acc += W @ Ks ----
        #pragma unroll 4
        for (int s = 0; s < BN; s += 4) {
            float4 a0 = *reinterpret_cast<const float4*>(&Ws[(ty4 + 0) * STRIDE + s]);
            float4 a1 = *reinterpret_cast<const float4*>(&Ws[(ty4 + 1) * STRIDE + s]);
            float4 a2 = *reinterpret_cast<const float4*>(&Ws[(ty4 + 2) * STRIDE + s]);
            float4 a3 = *reinterpret_cast<const float4*>(&Ws[(ty4 + 3) * STRIDE + s]);
            #pragma unroll
            for (int u = 0; u < 4; ++u) {
                float4 bv = *reinterpret_cast<const float4*>(&Ks[(s + u) * STRIDE + tx4]);
                float w0 = (u == 0) ? a0.x : (u == 1) ? a0.y : (u == 2) ? a0.z : a0.w;
                float w1 = (u == 0) ? a1.x : (u == 1) ? a1.y : (u == 2) ? a1.z : a1.w;
                float w2 = (u == 0) ? a2.x : (u == 1) ? a2.y : (u == 2) ? a2.z : a2.w;
                float w3 = (u == 0) ? a3.x : (u == 1) ? a3.y : (u == 2) ? a3.z : a3.w;
                acc[0][0] = fmaf(w0, bv.x, acc[0][0]);
                acc[0][1] = fmaf(w0, bv.y, acc[0][1]);
                acc[0][2] = fmaf(w0, bv.z, acc[0][2]);
                acc[0][3] = fmaf(w0, bv.w, acc[0][3]);
                acc[1][0] = fmaf(w1, bv.x, acc[1][0]);
                acc[1][1] = fmaf(w1, bv.y, acc[1][1]);
                acc[1][2] = fmaf(w1, bv.z, acc[1][2]);
                acc[1][3] = fmaf(w1, bv.w, acc[1][3]);
                acc[2][0] = fmaf(w2, bv.x, acc[2][0]);
                acc[2][1] = fmaf(w2, bv.y, acc[2][1]);
                acc[2][2] = fmaf(w2, bv.z, acc[2][2]);
                acc[2][3] = fmaf(w2, bv.w, acc[2][3]);
                acc[3][0] = fmaf(w3, bv.x, acc[3][0]);
                acc[3][1] = fmaf(w3, bv.y, acc[3][1]);
                acc[3][2] = fmaf(w3, bv.z, acc[3][2]);
                acc[3][3] = fmaf(w3, bv.w, acc[3][3]);
            }
        }
    }

    // ---- epilogue: out = x + acc ----
    #pragma unroll
    for (int i = 0; i < 4; ++i) {
        int row = qbase + ty4 + i;
        float4 xv = *reinterpret_cast<const float4*>(&xb[row * CDIM + tx4]);
        float4 o;
        o.x = xv.x + acc[i][0];
        o.y = xv.y + acc[i][1];
        o.z = xv.z + acc[i][2];
        o.w = xv.w + acc[i][3];
        *reinterpret_cast<float4*>(&ob[row * CDIM + tx4]) = o;
    }
}

extern "C" void kernel_launch(void* const* d_in, const int* in_sizes, int n_in,
                              void* d_out, int out_size) {
    const float* x       = (const float*)d_in[0];
    const float* r_sigma = (const float*)d_in[1];
    float* out           = (float*)d_out;

    cudaFuncSetAttribute(k_attention_kernel,
                         cudaFuncAttributeMaxDynamicSharedMemorySize, SMEM_BYTES);

    dim3 grid(TDIM / BM, BATCH);
    k_attention_kernel<<<grid, THREADS, SMEM_BYTES>>>(x, r_sigma, out);
}

// round 8
// speedup vs baseline: 1.6870x; 1.6870x over previous
#include <cuda_runtime.h>
#include <cuda_bf16.h>
#include <cstdint>

// out = x + exp(-max(||qi||^2 - 2<qi,kj> + ||kj||^2, 0)*sigma) @ x
// B=32, T=2048, C=64 fp32.  mma.sync bf16 split-precision (3-pass) version.

#define BATCH   32
#define TDIM    2048
#define CDIM    64
#define TQ      128          // query rows per CTA
#define TK      128          // keys per tile
#define NTILES  (TDIM / TK)
#define THREADS 256

// smem: bf16 tiles with row stride 72 elems (144 B) for conflict-free ldmatrix
#define RSTR      72
#define RSTRB     144
#define TILE_B    (128 * RSTRB)      // 18432
#define OFF_QHI   0
#define OFF_QLO   (TILE_B)
#define OFF_KHI   (2 * TILE_B)
#define OFF_KLO   (3 * TILE_B)
#define OFF_SQK   (4 * TILE_B)       // 128 floats
#define OFF_SQQ   (OFF_SQK + 512)    // 128 floats
#define SMEM_DYN  (OFF_SQQ + 512)    // 74752 bytes

__device__ __forceinline__ uint32_t smem_u32(const void* p) {
    uint32_t a;
    asm("{ .reg .u64 t; cvta.to.shared.u64 t, %1; cvt.u32.u64 %0, t; }" : "=r"(a) : "l"(p));
    return a;
}

#define LDSM_X4(r, addr) \
    asm volatile("ldmatrix.sync.aligned.m8n8.x4.shared.b16 {%0,%1,%2,%3}, [%4];" \
        : "=r"((r)[0]), "=r"((r)[1]), "=r"((r)[2]), "=r"((r)[3]) : "r"(addr))

#define LDSM_X4_T(r, addr) \
    asm volatile("ldmatrix.sync.aligned.m8n8.x4.trans.shared.b16 {%0,%1,%2,%3}, [%4];" \
        : "=r"((r)[0]), "=r"((r)[1]), "=r"((r)[2]), "=r"((r)[3]) : "r"(addr))

#define MMA(dv, a, b0, b1) \
    asm volatile("mma.sync.aligned.m16n8k16.row.col.f32.bf16.bf16.f32 " \
        "{%0,%1,%2,%3}, {%4,%5,%6,%7}, {%8,%9}, {%0,%1,%2,%3};" \
        : "+f"((dv)[0]), "+f"((dv)[1]), "+f"((dv)[2]), "+f"((dv)[3]) \
        : "r"((a)[0]), "r"((a)[1]), "r"((a)[2]), "r"((a)[3]), "r"(b0), "r"(b1))

// pack two floats to bf16x2 (a -> low half, b -> high half) and bf16x2 of residuals
__device__ __forceinline__ void split2(float a, float b, uint32_t& hi, uint32_t& lo) {
    asm("cvt.rn.bf16x2.f32 %0, %1, %2;" : "=r"(hi) : "f"(b), "f"(a));
    float ha = __uint_as_float(hi << 16);
    float hb = __uint_as_float(hi & 0xFFFF0000u);
    float ra = a - ha, rb = b - hb;
    asm("cvt.rn.bf16x2.f32 %0, %1, %2;" : "=r"(lo) : "f"(rb), "f"(ra));
}

__global__ __launch_bounds__(THREADS, 2)
void k_attention_mma(const float* __restrict__ x,
                     const float* __restrict__ r_sigma,
                     float* __restrict__ out) {
    extern __shared__ char sm[];
    const uint32_t sb = smem_u32(sm);
    float* sqkArr = reinterpret_cast<float*>(sm + OFF_SQK);
    float* sqqArr = reinterpret_cast<float*>(sm + OFF_SQQ);

    const int tid   = threadIdx.x;
    const int lane  = tid & 31;
    const int wid   = tid >> 5;
    const int wbase = wid * 16;
    const int g     = lane >> 2;
    const int t2    = (lane & 3) * 2;

    const int b     = blockIdx.y;
    const int qbase = blockIdx.x * TQ;
    const float* xb = x + (size_t)b * TDIM * CDIM;
    float* ob       = out + (size_t)b * TDIM * CDIM;
    const float negs = -r_sigma[0];

    // ---- ldmatrix base addresses ----
    const uint32_t qAddrH = sb + OFF_QHI + (uint32_t)(wbase + (lane & 15)) * RSTRB + (lane >> 4) * 16;
    const uint32_t qAddrL = qAddrH + (OFF_QLO - OFF_QHI);
    const uint32_t kAddrH = sb + OFF_KHI + (uint32_t)((lane & 7) + ((lane >> 4) << 3)) * RSTRB
                            + ((lane >> 3) & 1) * 16;
    const uint32_t kAddrL = kAddrH + (OFF_KLO - OFF_KHI);
    const uint32_t xAddrH = sb + OFF_KHI + (uint32_t)(lane & 15) * RSTRB + (lane >> 4) * 16;
    const uint32_t xAddrL = xAddrH + (OFF_KLO - OFF_KHI);

    // ---- load Q tile -> bf16 hi/lo smem ----
    #pragma unroll
    for (int i = 0; i < 8; ++i) {
        int idx = tid + i * THREADS;       // float4 index over [128 rows][16]
        int r = idx >> 4, c4 = idx & 15;
        float4 v = *reinterpret_cast<const float4*>(&xb[(qbase + r) * CDIM + c4 * 4]);
        uint32_t h01, l01, h23, l23;
        split2(v.x, v.y, h01, l01);
        split2(v.z, v.w, h23, l23);
        uint32_t off = (uint32_t)r * RSTRB + (uint32_t)c4 * 8;
        *reinterpret_cast<uint2*>(sm + OFF_QHI + off) = make_uint2(h01, h23);
        *reinterpret_cast<uint2*>(sm + OFF_QLO + off) = make_uint2(l01, l23);
    }
    if (tid < 128) {
        const float4* qr = reinterpret_cast<const float4*>(&xb[(qbase + tid) * CDIM]);
        float s = 0.f;
        #pragma unroll
        for (int i = 0; i < 16; ++i) {
            float4 v = qr[i];
            s = fmaf(v.x, v.x, fmaf(v.y, v.y, fmaf(v.z, v.z, fmaf(v.w, v.w, s))));
        }
        sqqArr[tid] = s;
    }
    __syncthreads();

    const float sqq0 = sqqArr[wbase + g];
    const float sqq1 = sqqArr[wbase + g + 8];

    float oacc[8][4];
    #pragma unroll
    for (int i = 0; i < 8; ++i)
        #pragma unroll
        for (int j = 0; j < 4; ++j) oacc[i][j] = 0.f;

    for (int kt = 0; kt < NTILES; ++kt) {
        const int kbase = kt * TK;
        __syncthreads();   // previous iter's ldmatrix reads of K done

        // ---- load K tile -> bf16 hi/lo smem ----
        #pragma unroll
        for (int i = 0; i < 8; ++i) {
            int idx = tid + i * THREADS;
            int r = idx >> 4, c4 = idx & 15;
            float4 v = *reinterpret_cast<const float4*>(&xb[(kbase + r) * CDIM + c4 * 4]);
            uint32_t h01, l01, h23, l23;
            split2(v.x, v.y, h01, l01);
            split2(v.z, v.w, h23, l23);
            uint32_t off = (uint32_t)r * RSTRB + (uint32_t)c4 * 8;
            *reinterpret_cast<uint2*>(sm + OFF_KHI + off) = make_uint2(h01, h23);
            *reinterpret_cast<uint2*>(sm + OFF_KLO + off) = make_uint2(l01, l23);
        }
        if (tid < 128) {
            const float4* kr = reinterpret_cast<const float4*>(&xb[(kbase + tid) * CDIM]);
            float s = 0.f;
            #pragma unroll
            for (int i = 0; i < 16; ++i) {
                float4 v = kr[i];
                s = fmaf(v.x, v.x, fmaf(v.y, v.y, fmaf(v.z, v.z, fmaf(v.w, v.w, s))));
            }
            sqkArr[tid] = s;
        }
        __syncthreads();

        // ---- GEMM1: S = Q.K^T, 3 split passes ----
        float sacc[16][4];
        #pragma unroll
        for (int i = 0; i < 16; ++i)
            #pragma unroll
            for (int j = 0; j < 4; ++j) sacc[i][j] = 0.f;

        #pragma unroll
        for (int kc = 0; kc < 4; ++kc) {
            uint32_t aH[4], aL[4];
            LDSM_X4(aH, qAddrH + kc * 32);
            LDSM_X4(aL, qAddrL + kc * 32);
            #pragma unroll
            for (int np = 0; np < 8; ++np) {
                uint32_t bH[4], bL[4];
                LDSM_X4(bH, kAddrH + np * 2304 + kc * 32);
                LDSM_X4(bL, kAddrL + np * 2304 + kc * 32);
                MMA(sacc[2 * np],     aH, bH[0], bH[1]);
                MMA(sacc[2 * np + 1], aH, bH[2], bH[3]);
                MMA(sacc[2 * np],     aH, bL[0], bL[1]);
                MMA(sacc[2 * np + 1], aH, bL[2], bL[3]);
                MMA(sacc[2 * np],     aL, bH[0], bH[1]);
                MMA(sacc[2 * np + 1], aL, bH[2], bH[3]);
            }
        }

        // ---- epilogue + GEMM2 per 16-wide s-chunk ----
        #pragma unroll
        for (int sc = 0; sc < 8; ++sc) {
            float* s0 = sacc[2 * sc];
            float* s1 = sacc[2 * sc + 1];
            float sk0 = sqkArr[sc * 16 + t2];
            float sk1 = sqkArr[sc * 16 + t2 + 1];
            float sk2 = sqkArr[sc * 16 + 8 + t2];
            float sk3 = sqkArr[sc * 16 + 8 + t2 + 1];
            float w00 = __expf(negs * fmaxf(sqq0 + sk0 - 2.f * s0[0], 0.f));
            float w01 = __expf(negs * fmaxf(sqq0 + sk1 - 2.f * s0[1], 0.f));
            float w02 = __expf(negs * fmaxf(sqq1 + sk0 - 2.f * s0[2], 0.f));
            float w03 = __expf(negs * fmaxf(sqq1 + sk1 - 2.f * s0[3], 0.f));
            float w10 = __expf(negs * fmaxf(sqq0 + sk2 - 2.f * s1[0], 0.f));
            float w11 = __expf(negs * fmaxf(sqq0 + sk3 - 2.f * s1[1], 0.f));
            float w12 = __expf(negs * fmaxf(sqq1 + sk2 - 2.f * s1[2], 0.f));
            float w13 = __expf(negs * fmaxf(sqq1 + sk3 - 2.f * s1[3], 0.f));

            uint32_t wh[4], wl[4];
            split2(w00, w01, wh[0], wl[0]);
            split2(w02, w03, wh[1], wl[1]);
            split2(w10, w11, wh[2], wl[2]);
            split2(w12, w13, wh[3], wl[3]);

            #pragma unroll
            for (int cp = 0; cp < 4; ++cp) {
                uint32_t bH[4], bL[4];
                LDSM_X4_T(bH, xAddrH + sc * 2304 + cp * 32);
                LDSM_X4_T(bL, xAddrL + sc * 2304 + cp * 32);
                MMA(oacc[2 * cp],     wh, bH[0], bH[1]);
                MMA(oacc[2 * cp + 1], wh, bH[2], bH[3]);
                MMA(oacc[2 * cp],     wh, bL[0], bL[1]);
                MMA(oacc[2 * cp + 1], wh, bL[2], bL[3]);
                MMA(oacc[2 * cp],     wl, bH[0], bH[1]);
                MMA(oacc[2 * cp + 1], wl, bH[2], bH[3]);
            }
        }
    }

    // ---- final: out = x + O ----
    const int r0 = qbase + wbase + g;
    const int r1 = r0 + 8;
    #pragma unroll
    for (int nt = 0; nt < 8; ++nt) {
        int c = nt * 8 + t2;
        float2 x0 = *reinterpret_cast<const float2*>(&xb[r0 * CDIM + c]);
        float2 x1 = *reinterpret_cast<const float2*>(&xb[r1 * CDIM + c]);
        float2 o0 = make_float2(x0.x + oacc[nt][0], x0.y + oacc[nt][1]);
        float2 o1 = make_float2(x1.x + oacc[nt][2], x1.y + oacc[nt][3]);
        *reinterpret_cast<float2*>(&ob[r0 * CDIM + c]) = o0;
        *reinterpret_cast<float2*>(&ob[r1 * CDIM + c]) = o1;
    }
}

extern "C" void kernel_launch(void* const* d_in, const int* in_sizes, int n_in,
                              void* d_out, int out_size) {
    const float* x       = (const float*)d_in[0];
    const float* r_sigma = (const float*)d_in[1];
    float* out           = (float*)d_out;

    cudaFuncSetAttribute(k_attention_mma,
                         cudaFuncAttributeMaxDynamicSharedMemorySize, SMEM_DYN);

    dim3 grid(TDIM / TQ, BATCH);
    k_attention_mma<<<grid, THREADS, SMEM_DYN>>>(x, r_sigma, out);
}

// round 10
// speedup vs baseline: 3.1552x; 1.8703x over previous
#include <cuda_runtime.h>
#include <cuda_bf16.h>
#include <cstdint>

// out = x + exp(-max(||qi||^2 - 2<qi,kj> + ||kj||^2, 0)*sigma) @ x
// B=32, T=2048, C=64 fp32.
// mma.sync bf16 split precision: GEMM1 3-pass (qH.kH + qH.kL + qL.kH),
// GEMM2 3-pass (wH.xH + wH.xL + wL.xH).  Double-buffered K tiles,
// register-prefetched loads, Q fragments (hi+lo) hoisted, 1 sync/tile.

#define BATCH   32
#define TDIM    2048
#define CDIM    64
#define TQ      128
#define TK      128
#define NTILES  (TDIM / TK)
#define THREADS 256

#define RSTRB       144               // 72 bf16 row stride
#define TILE_B      (128 * RSTRB)     // 18432
#define OFF_Q       0                 // Q hi tile
#define OFF_K       18432             // K buffers: buf*36864 (+0 hi, +18432 lo)
#define KBUF_STRIDE 36864
#define OFF_SQK     92160             // 2 x 128 floats (double-buffered norms)
#define OFF_SQQ     93184             // 128 floats
#define SMEM_DYN    93696

__device__ __forceinline__ uint32_t smem_u32(const void* p) {
    uint32_t a;
    asm("{ .reg .u64 t; cvta.to.shared.u64 t, %1; cvt.u32.u64 %0, t; }" : "=r"(a) : "l"(p));
    return a;
}

#define LDSM_X4(r, addr) \
    asm volatile("ldmatrix.sync.aligned.m8n8.x4.shared.b16 {%0,%1,%2,%3}, [%4];" \
        : "=r"((r)[0]), "=r"((r)[1]), "=r"((r)[2]), "=r"((r)[3]) : "r"(addr))

#define LDSM_X4_T(r, addr) \
    asm volatile("ldmatrix.sync.aligned.m8n8.x4.trans.shared.b16 {%0,%1,%2,%3}, [%4];" \
        : "=r"((r)[0]), "=r"((r)[1]), "=r"((r)[2]), "=r"((r)[3]) : "r"(addr))

#define MMA(dv, a, b0, b1) \
    asm volatile("mma.sync.aligned.m16n8k16.row.col.f32.bf16.bf16.f32 " \
        "{%0,%1,%2,%3}, {%4,%5,%6,%7}, {%8,%9}, {%0,%1,%2,%3};" \
        : "+f"((dv)[0]), "+f"((dv)[1]), "+f"((dv)[2]), "+f"((dv)[3]) \
        : "r"((a)[0]), "r"((a)[1]), "r"((a)[2]), "r"((a)[3]), "r"(b0), "r"(b1))

// pack (a,b) -> bf16x2 hi, residuals -> bf16x2 lo
__device__ __forceinline__ void split2(float a, float b, uint32_t& hi, uint32_t& lo) {
    asm("cvt.rn.bf16x2.f32 %0, %1, %2;" : "=r"(hi) : "f"(b), "f"(a));
    float ha = __uint_as_float(hi << 16);
    float hb = __uint_as_float(hi & 0xFFFF0000u);
    float ra = a - ha, rb = b - hb;
    asm("cvt.rn.bf16x2.f32 %0, %1, %2;" : "=r"(lo) : "f"(rb), "f"(ra));
}

__global__ __launch_bounds__(THREADS, 2)
void k_attention_mma3(const float* __restrict__ x,
                      const float* __restrict__ r_sigma,
                      float* __restrict__ out) {
    extern __shared__ char sm[];
    const uint32_t sb = smem_u32(sm);
    float* sqqArr = reinterpret_cast<float*>(sm + OFF_SQQ);

    const int tid   = threadIdx.x;
    const int lane  = tid & 31;
    const int wid   = tid >> 5;
    const int wbase = wid * 16;
    const int g     = lane >> 2;
    const int t2    = (lane & 3) * 2;
    const int gr16  = tid >> 4;
    const int c4    = tid & 15;

    const int b     = blockIdx.y;
    const int qbase = blockIdx.x * TQ;
    const float* xb = x + (size_t)b * TDIM * CDIM;
    float* ob       = out + (size_t)b * TDIM * CDIM;
    const float negs = -r_sigma[0];

    const uint32_t qfragOff = (uint32_t)(wbase + (lane & 15)) * RSTRB + (lane >> 4) * 16;
    const uint32_t qAddr    = sb + OFF_Q + qfragOff;
    const uint32_t qloAddr  = sb + OFF_K + KBUF_STRIDE + qfragOff;  // staged in buf1
    const uint32_t kAddrH = sb + OFF_K + (uint32_t)((lane & 7) + ((lane >> 4) << 3)) * RSTRB
                            + ((lane >> 3) & 1) * 16;
    const uint32_t xAddrH = sb + OFF_K + (uint32_t)(lane & 15) * RSTRB + (lane >> 4) * 16;

    // ---- prologue: Q tile hi -> OFF_Q, Q lo staged in K buffer 1 ----
    #pragma unroll
    for (int i = 0; i < 8; ++i) {
        int r = gr16 + 16 * i;
        float4 v = *reinterpret_cast<const float4*>(&xb[(qbase + r) * CDIM + c4 * 4]);
        uint32_t h01, l01, h23, l23;
        split2(v.x, v.y, h01, l01);
        split2(v.z, v.w, h23, l23);
        uint32_t off = (uint32_t)r * RSTRB + (uint32_t)c4 * 8;
        *reinterpret_cast<uint2*>(sm + OFF_Q + off) = make_uint2(h01, h23);
        *reinterpret_cast<uint2*>(sm + OFF_K + KBUF_STRIDE + off) = make_uint2(l01, l23);
    }
    // ---- prologue: K tile 0 (hi/lo) into buf0 + key norms via shuffle ----
    {
        float p[8];
        #pragma unroll
        for (int i = 0; i < 8; ++i) {
            int r = gr16 + 16 * i;
            float4 v = *reinterpret_cast<const float4*>(&xb[r * CDIM + c4 * 4]);
            uint32_t h01, l01, h23, l23;
            split2(v.x, v.y, h01, l01);
            split2(v.z, v.w, h23, l23);
            uint32_t off = (uint32_t)r * RSTRB + (uint32_t)c4 * 8;
            *reinterpret_cast<uint2*>(sm + OFF_K + off) = make_uint2(h01, h23);
            *reinterpret_cast<uint2*>(sm + OFF_K + 18432 + off) = make_uint2(l01, l23);
            p[i] = fmaf(v.x, v.x, fmaf(v.y, v.y, fmaf(v.z, v.z, v.w * v.w)));
        }
        #pragma unroll
        for (int i = 0; i < 8; ++i) {
            #pragma unroll
            for (int m = 1; m < 16; m <<= 1)
                p[i] += __shfl_xor_sync(0xFFFFFFFFu, p[i], m);
        }
        if (c4 == 0) {
            float* sk0 = reinterpret_cast<float*>(sm + OFF_SQK);
            #pragma unroll
            for (int i = 0; i < 8; ++i) sk0[gr16 + 16 * i] = p[i];
        }
    }
    if (tid < 128) {
        const float4* qr = reinterpret_cast<const float4*>(&xb[(qbase + tid) * CDIM]);
        float s = 0.f;
        #pragma unroll
        for (int i = 0; i < 16; ++i) {
            float4 v = qr[i];
            s = fmaf(v.x, v.x, fmaf(v.y, v.y, fmaf(v.z, v.z, fmaf(v.w, v.w, s))));
        }
        sqqArr[tid] = s;
    }
    __syncthreads();

    const float sqq0 = sqqArr[wbase + g];
    const float sqq1 = sqqArr[wbase + g + 8];

    // ---- Q fragments (hi + lo), loaded once; lo read from staging in buf1 ----
    uint32_t aH[4][4], aL[4][4];
    #pragma unroll
    for (int kc = 0; kc < 4; ++kc) {
        LDSM_X4(aH[kc], qAddr + kc * 32);
        LDSM_X4(aL[kc], qloAddr + kc * 32);
    }
    __syncthreads();   // aL reads done before buf1 is overwritten by prefetch

    float oacc[8][4];
    #pragma unroll
    for (int i = 0; i < 8; ++i)
        #pragma unroll
        for (int j = 0; j < 4; ++j) oacc[i][j] = 0.f;

    for (int kt = 0; kt < NTILES; ++kt) {
        const uint32_t bufOff  = (uint32_t)(kt & 1) * KBUF_STRIDE;
        const uint32_t nbufOff = bufOff ^ KBUF_STRIDE;
        const float* skb = reinterpret_cast<const float*>(sm + OFF_SQK + (kt & 1) * 512);
        float* skn       = reinterpret_cast<float*>(sm + OFF_SQK + ((kt & 1) ^ 1) * 512);
        const bool haveNext = (kt + 1) < NTILES;
        const int nkbase = (kt + 1) * TK;

        float4 pf[4];
        float p[8];
        if (haveNext) {
            #pragma unroll
            for (int j = 0; j < 4; ++j) {
                int r = gr16 + 16 * j;
                pf[j] = *reinterpret_cast<const float4*>(&xb[(nkbase + r) * CDIM + c4 * 4]);
            }
        }

        auto process_np = [&](int np) {
            float s0[4] = {0.f, 0.f, 0.f, 0.f};
            float s1[4] = {0.f, 0.f, 0.f, 0.f};
            #pragma unroll
            for (int kc = 0; kc < 4; ++kc) {
                uint32_t bH[4], bL[4];
                uint32_t ka = kAddrH + bufOff + (uint32_t)np * 2304 + kc * 32;
                LDSM_X4(bH, ka);
                LDSM_X4(bL, ka + 18432);
                MMA(s0, aH[kc], bH[0], bH[1]);
                MMA(s1, aH[kc], bH[2], bH[3]);
                MMA(s0, aH[kc], bL[0], bL[1]);
                MMA(s1, aH[kc], bL[2], bL[3]);
                MMA(s0, aL[kc], bH[0], bH[1]);
                MMA(s1, aL[kc], bH[2], bH[3]);
            }
            float sk0 = skb[np * 16 + t2];
            float sk1 = skb[np * 16 + t2 + 1];
            float sk2 = skb[np * 16 + 8 + t2];
            float sk3 = skb[np * 16 + 8 + t2 + 1];
            float w00 = __expf(negs * fmaxf(sqq0 + sk0 - 2.f * s0[0], 0.f));
            float w01 = __expf(negs * fmaxf(sqq0 + sk1 - 2.f * s0[1], 0.f));
            float w02 = __expf(negs * fmaxf(sqq1 + sk0 - 2.f * s0[2], 0.f));
            float w03 = __expf(negs * fmaxf(sqq1 + sk1 - 2.f * s0[3], 0.f));
            float w10 = __expf(negs * fmaxf(sqq0 + sk2 - 2.f * s1[0], 0.f));
            float w11 = __expf(negs * fmaxf(sqq0 + sk3 - 2.f * s1[1], 0.f));
            float w12 = __expf(negs * fmaxf(sqq1 + sk2 - 2.f * s1[2], 0.f));
            float w13 = __expf(negs * fmaxf(sqq1 + sk3 - 2.f * s1[3], 0.f));

            uint32_t wh[4], wl[4];
            split2(w00, w01, wh[0], wl[0]);
            split2(w02, w03, wh[1], wl[1]);
            split2(w10, w11, wh[2], wl[2]);
            split2(w12, w13, wh[3], wl[3]);

            #pragma unroll
            for (int cp = 0; cp < 4; ++cp) {
                uint32_t bH[4], bL[4];
                uint32_t xa = xAddrH + bufOff + (uint32_t)np * 2304 + cp * 32;
                LDSM_X4_T(bH, xa);
                LDSM_X4_T(bL, xa + 18432);
                MMA(oacc[2 * cp],     wh, bH[0], bH[1]);
                MMA(oacc[2 * cp + 1], wh, bH[2], bH[3]);
                MMA(oacc[2 * cp],     wh, bL[0], bL[1]);
                MMA(oacc[2 * cp + 1], wh, bL[2], bL[3]);
                MMA(oacc[2 * cp],     wl, bH[0], bH[1]);
                MMA(oacc[2 * cp + 1], wl, bH[2], bH[3]);
            }
        };

        #pragma unroll
        for (int np = 0; np < 4; ++np) process_np(np);

        if (haveNext) {
            #pragma unroll
            for (int j = 0; j < 4; ++j) {
                int r = gr16 + 16 * j;
                float4 v = pf[j];
                uint32_t h01, l01, h23, l23;
                split2(v.x, v.y, h01, l01);
                split2(v.z, v.w, h23, l23);
                uint32_t off = (uint32_t)r * RSTRB + (uint32_t)c4 * 8;
                *reinterpret_cast<uint2*>(sm + OFF_K + nbufOff + off) = make_uint2(h01, h23);
                *reinterpret_cast<uint2*>(sm + OFF_K + nbufOff + 18432 + off) = make_uint2(l01, l23);
                p[j] = fmaf(v.x, v.x, fmaf(v.y, v.y, fmaf(v.z, v.z, v.w * v.w)));
            }
            #pragma unroll
            for (int j = 0; j < 4; ++j) {
                int r = gr16 + 16 * (4 + j);
                pf[j] = *reinterpret_cast<const float4*>(&xb[(nkbase + r) * CDIM + c4 * 4]);
            }
        }

        #pragma unroll
        for (int np = 4; np < 8; ++np) process_np(np);

        if (haveNext) {
            #pragma unroll
            for (int j = 0; j < 4; ++j) {
                int r = gr16 + 16 * (4 + j);
                float4 v = pf[j];
                uint32_t h01, l01, h23, l23;
                split2(v.x, v.y, h01, l01);
                split2(v.z, v.w, h23, l23);
                uint32_t off = (uint32_t)r * RSTRB + (uint32_t)c4 * 8;
                *reinterpret_cast<uint2*>(sm + OFF_K + nbufOff + off) = make_uint2(h01, h23);
                *reinterpret_cast<uint2*>(sm + OFF_K + nbufOff + 18432 + off) = make_uint2(l01, l23);
                p[4 + j] = fmaf(v.x, v.x, fmaf(v.y, v.y, fmaf(v.z, v.z, v.w * v.w)));
            }
            #pragma unroll
            for (int i = 0; i < 8; ++i) {
                #pragma unroll
                for (int m = 1; m < 16; m <<= 1)
                    p[i] += __shfl_xor_sync(0xFFFFFFFFu, p[i], m);
            }
            if (c4 == 0) {
                #pragma unroll
                for (int i = 0; i < 8; ++i) skn[gr16 + 16 * i] = p[i];
            }
        }
        __syncthreads();
    }

    // ---- final: out = x + O ----
    const int r0 = qbase + wbase + g;
    const int r1 = r0 + 8;
    #pragma unroll
    for (int nt = 0; nt < 8; ++nt) {
        int c = nt * 8 + t2;
        float2 x0 = *reinterpret_cast<const float2*>(&xb[r0 * CDIM + c]);
        float2 x1 = *reinterpret_cast<const float2*>(&xb[r1 * CDIM + c]);
        float2 o0 = make_float2(x0.x + oacc[nt][0], x0.y + oacc[nt][1]);
        float2 o1 = make_float2(x1.x + oacc[nt][2], x1.y + oacc[nt][3]);
        *reinterpret_cast<float2*>(&ob[r0 * CDIM + c]) = o0;
        *reinterpret_cast<float2*>(&ob[r1 * CDIM + c]) = o1;
    }
}

extern "C" void kernel_launch(void* const* d_in, const int* in_sizes, int n_in,
                              void* d_out, int out_size) {
    const float* x       = (const float*)d_in[0];
    const float* r_sigma = (const float*)d_in[1];
    float* out           = (float*)d_out;

    cudaFuncSetAttribute(k_attention_mma3,
                         cudaFuncAttributeMaxDynamicSharedMemorySize, SMEM_DYN);

    dim3 grid(TDIM / TQ, BATCH);
    k_attention_mma3<<<grid, THREADS, SMEM_DYN>>>(x, r_sigma, out);
}

// round 11
// speedup vs baseline: 3.5965x; 1.1399x over previous
#include <cuda_runtime.h>
#include <cuda_fp16.h>
#include <cstdint>

// out = x + exp(-max(||qi||^2 - 2<qi,kj> + ||kj||^2, 0)*sigma) @ x
// B=32, T=2048, C=64 fp32.
// mma.sync fp16 split precision: GEMM1 2-pass (qH.kH + qH.kL),
// GEMM2 3-pass (wH.xH + wH.xL + wL.xH).  Double-buffered K tiles,
// register-prefetched loads, Q fragments hoisted, 1 sync/tile.

#define BATCH   32
#define TDIM    2048
#define CDIM    64
#define TQ      128
#define TK      128
#define NTILES  (TDIM / TK)
#define THREADS 256

#define RSTRB       144               // 72 fp16 row stride
#define TILE_B      (128 * RSTRB)     // 18432
#define OFF_Q       0                 // Q hi tile
#define OFF_K       18432             // K buffers: buf*36864 (+0 hi, +18432 lo)
#define KBUF_STRIDE 36864
#define OFF_SQK     92160             // 2 x 128 floats (double-buffered norms)
#define OFF_SQQ     93184             // 128 floats
#define SMEM_DYN    93696

__device__ __forceinline__ uint32_t smem_u32(const void* p) {
    uint32_t a;
    asm("{ .reg .u64 t; cvta.to.shared.u64 t, %1; cvt.u32.u64 %0, t; }" : "=r"(a) : "l"(p));
    return a;
}

#define LDSM_X4(r, addr) \
    asm volatile("ldmatrix.sync.aligned.m8n8.x4.shared.b16 {%0,%1,%2,%3}, [%4];" \
        : "=r"((r)[0]), "=r"((r)[1]), "=r"((r)[2]), "=r"((r)[3]) : "r"(addr))

#define LDSM_X4_T(r, addr) \
    asm volatile("ldmatrix.sync.aligned.m8n8.x4.trans.shared.b16 {%0,%1,%2,%3}, [%4];" \
        : "=r"((r)[0]), "=r"((r)[1]), "=r"((r)[2]), "=r"((r)[3]) : "r"(addr))

#define MMA(dv, a, b0, b1) \
    asm volatile("mma.sync.aligned.m16n8k16.row.col.f32.f16.f16.f32 " \
        "{%0,%1,%2,%3}, {%4,%5,%6,%7}, {%8,%9}, {%0,%1,%2,%3};" \
        : "+f"((dv)[0]), "+f"((dv)[1]), "+f"((dv)[2]), "+f"((dv)[3]) \
        : "r"((a)[0]), "r"((a)[1]), "r"((a)[2]), "r"((a)[3]), "r"(b0), "r"(b1))

// (a,b) -> f16x2 hi (a low, b high), residuals -> f16x2 lo
__device__ __forceinline__ void split2(float a, float b, uint32_t& hi, uint32_t& lo) {
    __half2 h2 = __floats2half2_rn(a, b);
    hi = *reinterpret_cast<uint32_t*>(&h2);
    float ha = __low2float(h2), hb = __high2float(h2);
    __half2 l2 = __floats2half2_rn(a - ha, b - hb);
    lo = *reinterpret_cast<uint32_t*>(&l2);
}

__device__ __forceinline__ uint32_t pack_hi(float a, float b) {
    __half2 h2 = __floats2half2_rn(a, b);
    return *reinterpret_cast<uint32_t*>(&h2);
}

__global__ __launch_bounds__(THREADS, 2)
void k_attention_mma4(const float* __restrict__ x,
                      const float* __restrict__ r_sigma,
                      float* __restrict__ out) {
    extern __shared__ char sm[];
    const uint32_t sb = smem_u32(sm);
    float* sqqArr = reinterpret_cast<float*>(sm + OFF_SQQ);

    const int tid   = threadIdx.x;
    const int lane  = tid & 31;
    const int wid   = tid >> 5;
    const int wbase = wid * 16;
    const int g     = lane >> 2;
    const int t2    = (lane & 3) * 2;
    const int gr16  = tid >> 4;
    const int c4    = tid & 15;

    const int b     = blockIdx.y;
    const int qbase = blockIdx.x * TQ;
    const float* xb = x + (size_t)b * TDIM * CDIM;
    float* ob       = out + (size_t)b * TDIM * CDIM;
    const float negs = -r_sigma[0];

    const uint32_t qAddr  = sb + OFF_Q + (uint32_t)(wbase + (lane & 15)) * RSTRB + (lane >> 4) * 16;
    const uint32_t kAddrH = sb + OFF_K + (uint32_t)((lane & 7) + ((lane >> 4) << 3)) * RSTRB
                            + ((lane >> 3) & 1) * 16;
    const uint32_t xAddrH = sb + OFF_K + (uint32_t)(lane & 15) * RSTRB + (lane >> 4) * 16;

    // ---- prologue: Q tile (hi only) ----
    #pragma unroll
    for (int i = 0; i < 8; ++i) {
        int r = gr16 + 16 * i;
        float4 v = *reinterpret_cast<const float4*>(&xb[(qbase + r) * CDIM + c4 * 4]);
        uint32_t off = (uint32_t)r * RSTRB + (uint32_t)c4 * 8;
        *reinterpret_cast<uint2*>(sm + OFF_Q + off) =
            make_uint2(pack_hi(v.x, v.y), pack_hi(v.z, v.w));
    }
    // ---- prologue: K tile 0 (hi/lo) into buf0 + key norms via shuffle ----
    {
        float p[8];
        #pragma unroll
        for (int i = 0; i < 8; ++i) {
            int r = gr16 + 16 * i;
            float4 v = *reinterpret_cast<const float4*>(&xb[r * CDIM + c4 * 4]);
            uint32_t h01, l01, h23, l23;
            split2(v.x, v.y, h01, l01);
            split2(v.z, v.w, h23, l23);
            uint32_t off = (uint32_t)r * RSTRB + (uint32_t)c4 * 8;
            *reinterpret_cast<uint2*>(sm + OFF_K + off) = make_uint2(h01, h23);
            *reinterpret_cast<uint2*>(sm + OFF_K + 18432 + off) = make_uint2(l01, l23);
            p[i] = fmaf(v.x, v.x, fmaf(v.y, v.y, fmaf(v.z, v.z, v.w * v.w)));
        }
        #pragma unroll
        for (int i = 0; i < 8; ++i) {
            #pragma unroll
            for (int m = 1; m < 16; m <<= 1)
                p[i] += __shfl_xor_sync(0xFFFFFFFFu, p[i], m);
        }
        if (c4 == 0) {
            float* sk0 = reinterpret_cast<float*>(sm + OFF_SQK);
            #pragma unroll
            for (int i = 0; i < 8; ++i) sk0[gr16 + 16 * i] = p[i];
        }
    }
    if (tid < 128) {
        const float4* qr = reinterpret_cast<const float4*>(&xb[(qbase + tid) * CDIM]);
        float s = 0.f;
        #pragma unroll
        for (int i = 0; i < 16; ++i) {
            float4 v = qr[i];
            s = fmaf(v.x, v.x, fmaf(v.y, v.y, fmaf(v.z, v.z, fmaf(v.w, v.w, s))));
        }
        sqqArr[tid] = s;
    }
    __syncthreads();

    const float sqq0 = sqqArr[wbase + g];
    const float sqq1 = sqqArr[wbase + g + 8];

    // ---- Q fragments, loaded once ----
    uint32_t aH[4][4];
    #pragma unroll
    for (int kc = 0; kc < 4; ++kc) LDSM_X4(aH[kc], qAddr + kc * 32);

    float oacc[8][4];
    #pragma unroll
    for (int i = 0; i < 8; ++i)
        #pragma unroll
        for (int j = 0; j < 4; ++j) oacc[i][j] = 0.f;

    for (int kt = 0; kt < NTILES; ++kt) {
        const uint32_t bufOff  = (uint32_t)(kt & 1) * KBUF_STRIDE;
        const uint32_t nbufOff = bufOff ^ KBUF_STRIDE;
        const float* skb = reinterpret_cast<const float*>(sm + OFF_SQK + (kt & 1) * 512);
        float* skn       = reinterpret_cast<float*>(sm + OFF_SQK + ((kt & 1) ^ 1) * 512);
        const bool haveNext = (kt + 1) < NTILES;
        const int nkbase = (kt + 1) * TK;

        float4 pf[4];
        float p[8];
        if (haveNext) {
            #pragma unroll
            for (int j = 0; j < 4; ++j) {
                int r = gr16 + 16 * j;
                pf[j] = *reinterpret_cast<const float4*>(&xb[(nkbase + r) * CDIM + c4 * 4]);
            }
        }

        auto process_np = [&](int np) {
            float s0[4] = {0.f, 0.f, 0.f, 0.f};
            float s1[4] = {0.f, 0.f, 0.f, 0.f};
            #pragma unroll
            for (int kc = 0; kc < 4; ++kc) {
                uint32_t bH[4], bL[4];
                uint32_t ka = kAddrH + bufOff + (uint32_t)np * 2304 + kc * 32;
                LDSM_X4(bH, ka);
                LDSM_X4(bL, ka + 18432);
                MMA(s0, aH[kc], bH[0], bH[1]);
                MMA(s1, aH[kc], bH[2], bH[3]);
                MMA(s0, aH[kc], bL[0], bL[1]);
                MMA(s1, aH[kc], bL[2], bL[3]);
            }
            float sk0 = skb[np * 16 + t2];
            float sk1 = skb[np * 16 + t2 + 1];
            float sk2 = skb[np * 16 + 8 + t2];
            float sk3 = skb[np * 16 + 8 + t2 + 1];
            float w00 = __expf(negs * fmaxf(sqq0 + sk0 - 2.f * s0[0], 0.f));
            float w01 = __expf(negs * fmaxf(sqq0 + sk1 - 2.f * s0[1], 0.f));
            float w02 = __expf(negs * fmaxf(sqq1 + sk0 - 2.f * s0[2], 0.f));
            float w03 = __expf(negs * fmaxf(sqq1 + sk1 - 2.f * s0[3], 0.f));
            float w10 = __expf(negs * fmaxf(sqq0 + sk2 - 2.f * s1[0], 0.f));
            float w11 = __expf(negs * fmaxf(sqq0 + sk3 - 2.f * s1[1], 0.f));
            float w12 = __expf(negs * fmaxf(sqq1 + sk2 - 2.f * s1[2], 0.f));
            float w13 = __expf(negs * fmaxf(sqq1 + sk3 - 2.f * s1[3], 0.f));

            uint32_t wh[4], wl[4];
            split2(w00, w01, wh[0], wl[0]);
            split2(w02, w03, wh[1], wl[1]);
            split2(w10, w11, wh[2], wl[2]);
            split2(w12, w13, wh[3], wl[3]);

            #pragma unroll
            for (int cp = 0; cp < 4; ++cp) {
                uint32_t bH[4], bL[4];
                uint32_t xa = xAddrH + bufOff + (uint32_t)np * 2304 + cp * 32;
                LDSM_X4_T(bH, xa);
                LDSM_X4_T(bL, xa + 18432);
                MMA(oacc[2 * cp],     wh, bH[0], bH[1]);
                MMA(oacc[2 * cp + 1], wh, bH[2], bH[3]);
                MMA(oacc[2 * cp],     wh, bL[0], bL[1]);
                MMA(oacc[2 * cp + 1], wh, bL[2], bL[3]);
                MMA(oacc[2 * cp],     wl, bH[0], bH[1]);
                MMA(oacc[2 * cp + 1], wl, bH[2], bH[3]);
            }
        };

        #pragma unroll
        for (int np = 0; np < 4; ++np) process_np(np);

        if (haveNext) {
            #pragma unroll
            for (int j = 0; j < 4; ++j) {
                int r = gr16 + 16 * j;
                float4 v = pf[j];
                uint32_t h01, l01, h23, l23;
                split2(v.x, v.y, h01, l01);
                split2(v.z, v.w, h23, l23);
                uint32_t off = (uint32_t)r * RSTRB + (uint32_t)c4 * 8;
                *reinterpret_cast<uint2*>(sm + OFF_K + nbufOff + off) = make_uint2(h01, h23);
                *reinterpret_cast<uint2*>(sm + OFF_K + nbufOff + 18432 + off) = make_uint2(l01, l23);
                p[j] = fmaf(v.x, v.x, fmaf(v.y, v.y, fmaf(v.z, v.z, v.w * v.w)));
            }
            #pragma unroll
            for (int j = 0; j < 4; ++j) {
                int r = gr16 + 16 * (4 + j);
                pf[j] = *reinterpret_cast<const float4*>(&xb[(nkbase + r) * CDIM + c4 * 4]);
            }
        }

        #pragma unroll
        for (int np = 4; np < 8; ++np) process_np(np);

        if (haveNext) {
            #pragma unroll
            for (int j = 0; j < 4; ++j) {
                int r = gr16 + 16 * (4 + j);
                float4 v = pf[j];
                uint32_t h01, l01, h23, l23;
                split2(v.x, v.y, h01, l01);
                split2(v.z, v.w, h23, l23);
                uint32_t off = (uint32_t)r * RSTRB + (uint32_t)c4 * 8;
                *reinterpret_cast<uint2*>(sm + OFF_K + nbufOff + off) = make_uint2(h01, h23);
                *reinterpret_cast<uint2*>(sm + OFF_K + nbufOff + 18432 + off) = make_uint2(l01, l23);
                p[4 + j] = fmaf(v.x, v.x, fmaf(v.y, v.y, fmaf(v.z, v.z, v.w * v.w)));
            }
            #pragma unroll
            for (int i = 0; i < 8; ++i) {
                #pragma unroll
                for (int m = 1; m < 16; m <<= 1)
                    p[i] += __shfl_xor_sync(0xFFFFFFFFu, p[i], m);
            }
            if (c4 == 0) {
                #pragma unroll
                for (int i = 0; i < 8; ++i) skn[gr16 + 16 * i] = p[i];
            }
        }
        __syncthreads();
    }

    // ---- final: out = x + O ----
    const int r0 = qbase + wbase + g;
    const int r1 = r0 + 8;
    #pragma unroll
    for (int nt = 0; nt < 8; ++nt) {
        int c = nt * 8 + t2;
        float2 x0 = *reinterpret_cast<const float2*>(&xb[r0 * CDIM + c]);
        float2 x1 = *reinterpret_cast<const float2*>(&xb[r1 * CDIM + c]);
        float2 o0 = make_float2(x0.x + oacc[nt][0], x0.y + oacc[nt][1]);
        float2 o1 = make_float2(x1.x + oacc[nt][2], x1.y + oacc[nt][3]);
        *reinterpret_cast<float2*>(&ob[r0 * CDIM + c]) = o0;
        *reinterpret_cast<float2*>(&ob[r1 * CDIM + c]) = o1;
    }
}

extern "C" void kernel_launch(void* const* d_in, const int* in_sizes, int n_in,
                              void* d_out, int out_size) {
    const float* x       = (const float*)d_in[0];
    const float* r_sigma = (const float*)d_in[1];
    float* out           = (float*)d_out;

    cudaFuncSetAttribute(k_attention_mma4,
                         cudaFuncAttributeMaxDynamicSharedMemorySize, SMEM_DYN);

    dim3 grid(TDIM / TQ, BATCH);
    k_attention_mma4<<<grid, THREADS, SMEM_DYN>>>(x, r_sigma, out);
}

// round 12
// speedup vs baseline: 5.1987x; 1.4455x over previous
#include <cuda_runtime.h>
#include <cuda_fp16.h>
#include <cstdint>

// out = x + exp(-max(||qi||^2 - 2<qi,kj> + ||kj||^2, 0)*sigma) @ x
// B=32, T=2048, C=64 fp32.
// mma.sync fp16: GEMM1 1-pass (qH.kH), GEMM2 2-pass (wH.xH + wL.xH).
// Hi-only tiles (no residual tiles), double-buffered K, register prefetch,
// hoisted Q fragments, 1 sync/tile.

#define BATCH   32
#define TDIM    2048
#define CDIM    64
#define TQ      128
#define TK      128
#define NTILES  (TDIM / TK)
#define THREADS 256

#define RSTRB       144               // 72 fp16 row stride
#define TILE_B      (128 * RSTRB)     // 18432
#define OFF_Q       0                 // Q hi tile
#define OFF_K       18432             // K hi buffers: + buf*18432
#define KBUF_STRIDE 18432
#define OFF_SQK     55296             // 2 x 128 floats (double-buffered norms)
#define OFF_SQQ     56320             // 128 floats
#define SMEM_DYN    56832

__device__ __forceinline__ uint32_t smem_u32(const void* p) {
    uint32_t a;
    asm("{ .reg .u64 t; cvta.to.shared.u64 t, %1; cvt.u32.u64 %0, t; }" : "=r"(a) : "l"(p));
    return a;
}

#define LDSM_X4(r, addr) \
    asm volatile("ldmatrix.sync.aligned.m8n8.x4.shared.b16 {%0,%1,%2,%3}, [%4];" \
        : "=r"((r)[0]), "=r"((r)[1]), "=r"((r)[2]), "=r"((r)[3]) : "r"(addr))

#define LDSM_X4_T(r, addr) \
    asm volatile("ldmatrix.sync.aligned.m8n8.x4.trans.shared.b16 {%0,%1,%2,%3}, [%4];" \
        : "=r"((r)[0]), "=r"((r)[1]), "=r"((r)[2]), "=r"((r)[3]) : "r"(addr))

#define MMA(dv, a, b0, b1) \
    asm volatile("mma.sync.aligned.m16n8k16.row.col.f32.f16.f16.f32 " \
        "{%0,%1,%2,%3}, {%4,%5,%6,%7}, {%8,%9}, {%0,%1,%2,%3};" \
        : "+f"((dv)[0]), "+f"((dv)[1]), "+f"((dv)[2]), "+f"((dv)[3]) \
        : "r"((a)[0]), "r"((a)[1]), "r"((a)[2]), "r"((a)[3]), "r"(b0), "r"(b1))

// (a,b) -> f16x2 hi, residuals -> f16x2 lo
__device__ __forceinline__ void split2(float a, float b, uint32_t& hi, uint32_t& lo) {
    __half2 h2 = __floats2half2_rn(a, b);
    hi = *reinterpret_cast<uint32_t*>(&h2);
    float ha = __low2float(h2), hb = __high2float(h2);
    __half2 l2 = __floats2half2_rn(a - ha, b - hb);
    lo = *reinterpret_cast<uint32_t*>(&l2);
}

__device__ __forceinline__ uint32_t pack_hi(float a, float b) {
    __half2 h2 = __floats2half2_rn(a, b);
    return *reinterpret_cast<uint32_t*>(&h2);
}

__global__ __launch_bounds__(THREADS, 2)
void k_attention_mma5(const float* __restrict__ x,
                      const float* __restrict__ r_sigma,
                      float* __restrict__ out) {
    extern __shared__ char sm[];
    const uint32_t sb = smem_u32(sm);
    float* sqqArr = reinterpret_cast<float*>(sm + OFF_SQQ);

    const int tid   = threadIdx.x;
    const int lane  = tid & 31;
    const int wid   = tid >> 5;
    const int wbase = wid * 16;
    const int g     = lane >> 2;
    const int t2    = (lane & 3) * 2;
    const int gr16  = tid >> 4;
    const int c4    = tid & 15;

    const int b     = blockIdx.y;
    const int qbase = blockIdx.x * TQ;
    const float* xb = x + (size_t)b * TDIM * CDIM;
    float* ob       = out + (size_t)b * TDIM * CDIM;
    const float negs = -r_sigma[0];

    const uint32_t qAddr  = sb + OFF_Q + (uint32_t)(wbase + (lane & 15)) * RSTRB + (lane >> 4) * 16;
    const uint32_t kAddrH = sb + OFF_K + (uint32_t)((lane & 7) + ((lane >> 4) << 3)) * RSTRB
                            + ((lane >> 3) & 1) * 16;
    const uint32_t xAddrH = sb + OFF_K + (uint32_t)(lane & 15) * RSTRB + (lane >> 4) * 16;

    // ---- prologue: Q tile (hi) ----
    #pragma unroll
    for (int i = 0; i < 8; ++i) {
        int r = gr16 + 16 * i;
        float4 v = *reinterpret_cast<const float4*>(&xb[(qbase + r) * CDIM + c4 * 4]);
        uint32_t off = (uint32_t)r * RSTRB + (uint32_t)c4 * 8;
        *reinterpret_cast<uint2*>(sm + OFF_Q + off) =
            make_uint2(pack_hi(v.x, v.y), pack_hi(v.z, v.w));
    }
    // ---- prologue: K tile 0 (hi) into buf0 + key norms via shuffle ----
    {
        float p[8];
        #pragma unroll
        for (int i = 0; i < 8; ++i) {
            int r = gr16 + 16 * i;
            float4 v = *reinterpret_cast<const float4*>(&xb[r * CDIM + c4 * 4]);
            uint32_t off = (uint32_t)r * RSTRB + (uint32_t)c4 * 8;
            *reinterpret_cast<uint2*>(sm + OFF_K + off) =
                make_uint2(pack_hi(v.x, v.y), pack_hi(v.z, v.w));
            p[i] = fmaf(v.x, v.x, fmaf(v.y, v.y, fmaf(v.z, v.z, v.w * v.w)));
        }
        #pragma unroll
        for (int i = 0; i < 8; ++i) {
            #pragma unroll
            for (int m = 1; m < 16; m <<= 1)
                p[i] += __shfl_xor_sync(0xFFFFFFFFu, p[i], m);
        }
        if (c4 == 0) {
            float* sk0 = reinterpret_cast<float*>(sm + OFF_SQK);
            #pragma unroll
            for (int i = 0; i < 8; ++i) sk0[gr16 + 16 * i] = p[i];
        }
    }
    if (tid < 128) {
        const float4* qr = reinterpret_cast<const float4*>(&xb[(qbase + tid) * CDIM]);
        float s = 0.f;
        #pragma unroll
        for (int i = 0; i < 16; ++i) {
            float4 v = qr[i];
            s = fmaf(v.x, v.x, fmaf(v.y, v.y, fmaf(v.z, v.z, fmaf(v.w, v.w, s))));
        }
        sqqArr[tid] = s;
    }
    __syncthreads();

    const float sqq0 = sqqArr[wbase + g];
    const float sqq1 = sqqArr[wbase + g + 8];

    // ---- Q fragments, loaded once ----
    uint32_t aH[4][4];
    #pragma unroll
    for (int kc = 0; kc < 4; ++kc) LDSM_X4(aH[kc], qAddr + kc * 32);

    float oacc[8][4];
    #pragma unroll
    for (int i = 0; i < 8; ++i)
        #pragma unroll
        for (int j = 0; j < 4; ++j) oacc[i][j] = 0.f;

    for (int kt = 0; kt < NTILES; ++kt) {
        const uint32_t bufOff  = (uint32_t)(kt & 1) * KBUF_STRIDE;
        const uint32_t nbufOff = bufOff ^ KBUF_STRIDE;
        const float* skb = reinterpret_cast<const float*>(sm + OFF_SQK + (kt & 1) * 512);
        float* skn       = reinterpret_cast<float*>(sm + OFF_SQK + ((kt & 1) ^ 1) * 512);
        const bool haveNext = (kt + 1) < NTILES;
        const int nkbase = (kt + 1) * TK;

        float4 pf[4];
        float p[8];
        if (haveNext) {
            #pragma unroll
            for (int j = 0; j < 4; ++j) {
                int r = gr16 + 16 * j;
                pf[j] = *reinterpret_cast<const float4*>(&xb[(nkbase + r) * CDIM + c4 * 4]);
            }
        }

        auto process_np = [&](int np) {
            float s0[4] = {0.f, 0.f, 0.f, 0.f};
            float s1[4] = {0.f, 0.f, 0.f, 0.f};
            #pragma unroll
            for (int kc = 0; kc < 4; ++kc) {
                uint32_t bH[4];
                LDSM_X4(bH, kAddrH + bufOff + (uint32_t)np * 2304 + kc * 32);
                MMA(s0, aH[kc], bH[0], bH[1]);
                MMA(s1, aH[kc], bH[2], bH[3]);
            }
            float sk0 = skb[np * 16 + t2];
            float sk1 = skb[np * 16 + t2 + 1];
            float sk2 = skb[np * 16 + 8 + t2];
            float sk3 = skb[np * 16 + 8 + t2 + 1];
            float w00 = __expf(negs * fmaxf(sqq0 + sk0 - 2.f * s0[0], 0.f));
            float w01 = __expf(negs * fmaxf(sqq0 + sk1 - 2.f * s0[1], 0.f));
            float w02 = __expf(negs * fmaxf(sqq1 + sk0 - 2.f * s0[2], 0.f));
            float w03 = __expf(negs * fmaxf(sqq1 + sk1 - 2.f * s0[3], 0.f));
            float w10 = __expf(negs * fmaxf(sqq0 + sk2 - 2.f * s1[0], 0.f));
            float w11 = __expf(negs * fmaxf(sqq0 + sk3 - 2.f * s1[1], 0.f));
            float w12 = __expf(negs * fmaxf(sqq1 + sk2 - 2.f * s1[2], 0.f));
            float w13 = __expf(negs * fmaxf(sqq1 + sk3 - 2.f * s1[3], 0.f));

            uint32_t wh[4], wl[4];
            split2(w00, w01, wh[0], wl[0]);
            split2(w02, w03, wh[1], wl[1]);
            split2(w10, w11, wh[2], wl[2]);
            split2(w12, w13, wh[3], wl[3]);

            #pragma unroll
            for (int cp = 0; cp < 4; ++cp) {
                uint32_t bH[4];
                LDSM_X4_T(bH, xAddrH + bufOff + (uint32_t)np * 2304 + cp * 32);
                MMA(oacc[2 * cp],     wh, bH[0], bH[1]);
                MMA(oacc[2 * cp + 1], wh, bH[2], bH[3]);
                MMA(oacc[2 * cp],     wl, bH[0], bH[1]);
                MMA(oacc[2 * cp + 1], wl, bH[2], bH[3]);
            }
        };

        #pragma unroll
        for (int np = 0; np < 4; ++np) process_np(np);

        if (haveNext) {
            #pragma unroll
            for (int j = 0; j < 4; ++j) {
                int r = gr16 + 16 * j;
                float4 v = pf[j];
                uint32_t off = (uint32_t)r * RSTRB + (uint32_t)c4 * 8;
                *reinterpret_cast<uint2*>(sm + OFF_K + nbufOff + off) =
                    make_uint2(pack_hi(v.x, v.y), pack_hi(v.z, v.w));
                p[j] = fmaf(v.x, v.x, fmaf(v.y, v.y, fmaf(v.z, v.z, v.w * v.w)));
            }
            #pragma unroll
            for (int j = 0; j < 4; ++j) {
                int r = gr16 + 16 * (4 + j);
                pf[j] = *reinterpret_cast<const float4*>(&xb[(nkbase + r) * CDIM + c4 * 4]);
            }
        }

        #pragma unroll
        for (int np = 4; np < 8; ++np) process_np(np);

        if (haveNext) {
            #pragma unroll
            for (int j = 0; j < 4; ++j) {
                int r = gr16 + 16 * (4 + j);
                float4 v = pf[j];
                uint32_t off = (uint32_t)r * RSTRB + (uint32_t)c4 * 8;
                *reinterpret_cast<uint2*>(sm + OFF_K + nbufOff + off) =
                    make_uint2(pack_hi(v.x, v.y), pack_hi(v.z, v.w));
                p[4 + j] = fmaf(v.x, v.x, fmaf(v.y, v.y, fmaf(v.z, v.z, v.w * v.w)));
            }
            #pragma unroll
            for (int i = 0; i < 8; ++i) {
                #pragma unroll
                for (int m = 1; m < 16; m <<= 1)
                    p[i] += __shfl_xor_sync(0xFFFFFFFFu, p[i], m);
            }
            if (c4 == 0) {
                #pragma unroll
                for (int i = 0; i < 8; ++i) skn[gr16 + 16 * i] = p[i];
            }
        }
        __syncthreads();
    }

    // ---- final: out = x + O ----
    const int r0 = qbase + wbase + g;
    const int r1 = r0 + 8;
    #pragma unroll
    for (int nt = 0; nt < 8; ++nt) {
        int c = nt * 8 + t2;
        float2 x0 = *reinterpret_cast<const float2*>(&xb[r0 * CDIM + c]);
        float2 x1 = *reinterpret_cast<const float2*>(&xb[r1 * CDIM + c]);
        float2 o0 = make_float2(x0.x + oacc[nt][0], x0.y + oacc[nt][1]);
        float2 o1 = make_float2(x1.x + oacc[nt][2], x1.y + oacc[nt][3]);
        *reinterpret_cast<float2*>(&ob[r0 * CDIM + c]) = o0;
        *reinterpret_cast<float2*>(&ob[r1 * CDIM + c]) = o1;
    }
}

extern "C" void kernel_launch(void* const* d_in, const int* in_sizes, int n_in,
                              void* d_out, int out_size) {
    const float* x       = (const float*)d_in[0];
    const float* r_sigma = (const float*)d_in[1];
    float* out           = (float*)d_out;

    cudaFuncSetAttribute(k_attention_mma5,
                         cudaFuncAttributeMaxDynamicSharedMemorySize, SMEM_DYN);

    dim3 grid(TDIM / TQ, BATCH);
    k_attention_mma5<<<grid, THREADS, SMEM_DYN>>>(x, r_sigma, out);
}

// round 13
// speedup vs baseline: 6.3529x; 1.2220x over previous
#include <cuda_runtime.h>
#include <cuda_fp16.h>
#include <cstdint>

// out = x + exp(-max(||qi||^2 - 2<qi,kj> + ||kj||^2, 0)*sigma) @ x
// B=32, T=2048, C=64 fp32.
// Pure fp16 mma.sync: GEMM1 qH.kH, GEMM2 wH.xH.  Norms pre-scaled by
// -sigma*log2(e); w = ex2(min(nq+nk+p2*s,0)).  Double-buffered K tiles,
// chunked register prefetch, hoisted Q fragments, 1 sync/tile, 3 CTAs/SM.

#define BATCH   32
#define TDIM    2048
#define CDIM    64
#define TQ      128
#define TK      128
#define NTILES  (TDIM / TK)
#define THREADS 256

#define RSTRB       144               // 72 fp16 row stride
#define OFF_Q       0                 // Q hi tile (18432 B)
#define OFF_K       18432             // K hi buffers: + buf*18432
#define KBUF_STRIDE 18432
#define OFF_SQK     55296             // 2 x 128 floats (double-buffered, pre-scaled)
#define OFF_SQQ     56320             // 128 floats (pre-scaled)
#define SMEM_DYN    56832

__device__ __forceinline__ uint32_t smem_u32(const void* p) {
    uint32_t a;
    asm("{ .reg .u64 t; cvta.to.shared.u64 t, %1; cvt.u32.u64 %0, t; }" : "=r"(a) : "l"(p));
    return a;
}

__device__ __forceinline__ float ex2(float x) {
    float r;
    asm("ex2.approx.ftz.f32 %0, %1;" : "=f"(r) : "f"(x));
    return r;
}

#define LDSM_X4(r, addr) \
    asm volatile("ldmatrix.sync.aligned.m8n8.x4.shared.b16 {%0,%1,%2,%3}, [%4];" \
        : "=r"((r)[0]), "=r"((r)[1]), "=r"((r)[2]), "=r"((r)[3]) : "r"(addr))

#define LDSM_X4_T(r, addr) \
    asm volatile("ldmatrix.sync.aligned.m8n8.x4.trans.shared.b16 {%0,%1,%2,%3}, [%4];" \
        : "=r"((r)[0]), "=r"((r)[1]), "=r"((r)[2]), "=r"((r)[3]) : "r"(addr))

#define MMA(dv, a, b0, b1) \
    asm volatile("mma.sync.aligned.m16n8k16.row.col.f32.f16.f16.f32 " \
        "{%0,%1,%2,%3}, {%4,%5,%6,%7}, {%8,%9}, {%0,%1,%2,%3};" \
        : "+f"((dv)[0]), "+f"((dv)[1]), "+f"((dv)[2]), "+f"((dv)[3]) \
        : "r"((a)[0]), "r"((a)[1]), "r"((a)[2]), "r"((a)[3]), "r"(b0), "r"(b1))

__device__ __forceinline__ uint32_t pack_hi(float a, float b) {
    __half2 h2 = __floats2half2_rn(a, b);
    return *reinterpret_cast<uint32_t*>(&h2);
}

__global__ __launch_bounds__(THREADS, 3)
void k_attention_mma6(const float* __restrict__ x,
                      const float* __restrict__ r_sigma,
                      float* __restrict__ out) {
    extern __shared__ char sm[];
    const uint32_t sb = smem_u32(sm);
    float* sqqArr = reinterpret_cast<float*>(sm + OFF_SQQ);

    const int tid   = threadIdx.x;
    const int lane  = tid & 31;
    const int wid   = tid >> 5;
    const int wbase = wid * 16;
    const int g     = lane >> 2;
    const int t2    = (lane & 3) * 2;
    const int gr16  = tid >> 4;
    const int c4    = tid & 15;

    const int b     = blockIdx.y;
    const int qbase = blockIdx.x * TQ;
    const float* xb = x + (size_t)b * TDIM * CDIM;
    float* ob       = out + (size_t)b * TDIM * CDIM;
    // negs2 = -sigma * log2(e); p2 = -2*negs2
    const float negs2 = -r_sigma[0] * 1.4426950408889634f;
    const float p2    = -2.f * negs2;

    const uint32_t qAddr  = sb + OFF_Q + (uint32_t)(wbase + (lane & 15)) * RSTRB + (lane >> 4) * 16;
    const uint32_t kAddrH = sb + OFF_K + (uint32_t)((lane & 7) + ((lane >> 4) << 3)) * RSTRB
                            + ((lane >> 3) & 1) * 16;
    const uint32_t xAddrH = sb + OFF_K + (uint32_t)(lane & 15) * RSTRB + (lane >> 4) * 16;

    // ---- prologue: Q tile (hi) ----
    #pragma unroll
    for (int i = 0; i < 8; ++i) {
        int r = gr16 + 16 * i;
        float4 v = *reinterpret_cast<const float4*>(&xb[(qbase + r) * CDIM + c4 * 4]);
        uint32_t off = (uint32_t)r * RSTRB + (uint32_t)c4 * 8;
        *reinterpret_cast<uint2*>(sm + OFF_Q + off) =
            make_uint2(pack_hi(v.x, v.y), pack_hi(v.z, v.w));
    }
    // ---- prologue: K tile 0 (hi) into buf0 + pre-scaled key norms ----
    {
        float p[8];
        #pragma unroll
        for (int i = 0; i < 8; ++i) {
            int r = gr16 + 16 * i;
            float4 v = *reinterpret_cast<const float4*>(&xb[r * CDIM + c4 * 4]);
            uint32_t off = (uint32_t)r * RSTRB + (uint32_t)c4 * 8;
            *reinterpret_cast<uint2*>(sm + OFF_K + off) =
                make_uint2(pack_hi(v.x, v.y), pack_hi(v.z, v.w));
            p[i] = fmaf(v.x, v.x, fmaf(v.y, v.y, fmaf(v.z, v.z, v.w * v.w)));
        }
        #pragma unroll
        for (int i = 0; i < 8; ++i) {
            #pragma unroll
            for (int m = 1; m < 16; m <<= 1)
                p[i] += __shfl_xor_sync(0xFFFFFFFFu, p[i], m);
        }
        if (c4 == 0) {
            float* sk0 = reinterpret_cast<float*>(sm + OFF_SQK);
            #pragma unroll
            for (int i = 0; i < 8; ++i) sk0[gr16 + 16 * i] = negs2 * p[i];
        }
    }
    if (tid < 128) {
        const float4* qr = reinterpret_cast<const float4*>(&xb[(qbase + tid) * CDIM]);
        float s = 0.f;
        #pragma unroll
        for (int i = 0; i < 16; ++i) {
            float4 v = qr[i];
            s = fmaf(v.x, v.x, fmaf(v.y, v.y, fmaf(v.z, v.z, fmaf(v.w, v.w, s))));
        }
        sqqArr[tid] = negs2 * s;
    }
    __syncthreads();

    const float nq0 = sqqArr[wbase + g];        // pre-scaled
    const float nq1 = sqqArr[wbase + g + 8];

    // ---- Q fragments, loaded once ----
    uint32_t aH[4][4];
    #pragma unroll
    for (int kc = 0; kc < 4; ++kc) LDSM_X4(aH[kc], qAddr + kc * 32);

    float oacc[8][4];
    #pragma unroll
    for (int i = 0; i < 8; ++i)
        #pragma unroll
        for (int j = 0; j < 4; ++j) oacc[i][j] = 0.f;

    for (int kt = 0; kt < NTILES; ++kt) {
        const uint32_t bufOff  = (uint32_t)(kt & 1) * KBUF_STRIDE;
        const uint32_t nbufOff = bufOff ^ KBUF_STRIDE;
        const float* skb = reinterpret_cast<const float*>(sm + OFF_SQK + (kt & 1) * 512);
        float* skn       = reinterpret_cast<float*>(sm + OFF_SQK + ((kt & 1) ^ 1) * 512);
        const bool haveNext = (kt + 1) < NTILES;
        const int nkbase = (kt + 1) * TK;

        float p[8];

        auto process_np = [&](int np) {
            float s0[4] = {0.f, 0.f, 0.f, 0.f};
            float s1[4] = {0.f, 0.f, 0.f, 0.f};
            #pragma unroll
            for (int kc = 0; kc < 4; ++kc) {
                uint32_t bH[4];
                LDSM_X4(bH, kAddrH + bufOff + (uint32_t)np * 2304 + kc * 32);
                MMA(s0, aH[kc], bH[0], bH[1]);
                MMA(s1, aH[kc], bH[2], bH[3]);
            }
            float nk0 = skb[np * 16 + t2];
            float nk1 = skb[np * 16 + t2 + 1];
            float nk2 = skb[np * 16 + 8 + t2];
            float nk3 = skb[np * 16 + 8 + t2 + 1];
            float w00 = ex2(fminf(fmaf(p2, s0[0], nq0 + nk0), 0.f));
            float w01 = ex2(fminf(fmaf(p2, s0[1], nq0 + nk1), 0.f));
            float w02 = ex2(fminf(fmaf(p2, s0[2], nq1 + nk0), 0.f));
            float w03 = ex2(fminf(fmaf(p2, s0[3], nq1 + nk1), 0.f));
            float w10 = ex2(fminf(fmaf(p2, s1[0], nq0 + nk2), 0.f));
            float w11 = ex2(fminf(fmaf(p2, s1[1], nq0 + nk3), 0.f));
            float w12 = ex2(fminf(fmaf(p2, s1[2], nq1 + nk2), 0.f));
            float w13 = ex2(fminf(fmaf(p2, s1[3], nq1 + nk3), 0.f));

            uint32_t wh[4];
            wh[0] = pack_hi(w00, w01);
            wh[1] = pack_hi(w02, w03);
            wh[2] = pack_hi(w10, w11);
            wh[3] = pack_hi(w12, w13);

            #pragma unroll
            for (int cp = 0; cp < 4; ++cp) {
                uint32_t bH[4];
                LDSM_X4_T(bH, xAddrH + bufOff + (uint32_t)np * 2304 + cp * 32);
                MMA(oacc[2 * cp],     wh, bH[0], bH[1]);
                MMA(oacc[2 * cp + 1], wh, bH[2], bH[3]);
            }
        };

        // 4 chunks: prefetch 2 rows, run 2 np's, convert+store the 2 rows
        #pragma unroll
        for (int h = 0; h < 4; ++h) {
            float4 pf0, pf1;
            if (haveNext) {
                int r0 = gr16 + 16 * (2 * h);
                int r1 = gr16 + 16 * (2 * h + 1);
                pf0 = *reinterpret_cast<const float4*>(&xb[(nkbase + r0) * CDIM + c4 * 4]);
                pf1 = *reinterpret_cast<const float4*>(&xb[(nkbase + r1) * CDIM + c4 * 4]);
            }
            process_np(2 * h);
            process_np(2 * h + 1);
            if (haveNext) {
                int r0 = gr16 + 16 * (2 * h);
                int r1 = gr16 + 16 * (2 * h + 1);
                uint32_t o0 = (uint32_t)r0 * RSTRB + (uint32_t)c4 * 8;
                uint32_t o1 = (uint32_t)r1 * RSTRB + (uint32_t)c4 * 8;
                *reinterpret_cast<uint2*>(sm + OFF_K + nbufOff + o0) =
                    make_uint2(pack_hi(pf0.x, pf0.y), pack_hi(pf0.z, pf0.w));
                *reinterpret_cast<uint2*>(sm + OFF_K + nbufOff + o1) =
                    make_uint2(pack_hi(pf1.x, pf1.y), pack_hi(pf1.z, pf1.w));
                p[2 * h]     = fmaf(pf0.x, pf0.x, fmaf(pf0.y, pf0.y, fmaf(pf0.z, pf0.z, pf0.w * pf0.w)));
                p[2 * h + 1] = fmaf(pf1.x, pf1.x, fmaf(pf1.y, pf1.y, fmaf(pf1.z, pf1.z, pf1.w * pf1.w)));
            }
        }

        if (haveNext) {
            #pragma unroll
            for (int i = 0; i < 8; ++i) {
                #pragma unroll
                for (int m = 1; m < 16; m <<= 1)
                    p[i] += __shfl_xor_sync(0xFFFFFFFFu, p[i], m);
            }
            if (c4 == 0) {
                #pragma unroll
                for (int i = 0; i < 8; ++i) skn[gr16 + 16 * i] = negs2 * p[i];
            }
        }
        __syncthreads();
    }

    // ---- final: out = x + O ----
    const int r0 = qbase + wbase + g;
    const int r1 = r0 + 8;
    #pragma unroll
    for (int nt = 0; nt < 8; ++nt) {
        int c = nt * 8 + t2;
        float2 x0 = *reinterpret_cast<const float2*>(&xb[r0 * CDIM + c]);
        float2 x1 = *reinterpret_cast<const float2*>(&xb[r1 * CDIM + c]);
        float2 o0 = make_float2(x0.x + oacc[nt][0], x0.y + oacc[nt][1]);
        float2 o1 = make_float2(x1.x + oacc[nt][2], x1.y + oacc[nt][3]);
        *reinterpret_cast<float2*>(&ob[r0 * CDIM + c]) = o0;
        *reinterpret_cast<float2*>(&ob[r1 * CDIM + c]) = o1;
    }
}

extern "C" void kernel_launch(void* const* d_in, const int* in_sizes, int n_in,
                              void* d_out, int out_size) {
    const float* x       = (const float*)d_in[0];
    const float* r_sigma = (const float*)d_in[1];
    float* out           = (float*)d_out;

    cudaFuncSetAttribute(k_attention_mma6,
                         cudaFuncAttributeMaxDynamicSharedMemorySize, SMEM_DYN);

    dim3 grid(TDIM / TQ, BATCH);
    k_attention_mma6<<<grid, THREADS, SMEM_DYN>>>(x, r_sigma, out);
}